// round 14
// baseline (speedup 1.0000x reference)
#include <cuda_runtime.h>
#include <cuda_fp16.h>
#include <cstdint>

// Problem dims (fixed for this dataset)
#define MAXN 100000
#define MAXE 1600000
#define FIN  784
#define D1   128
#define D2   256

// ---------------- scratch (device globals; no allocs allowed) ----------------
__device__ __half g_h1[(size_t)MAXN * D1];   // x@W1 (fp16, gather payload)
__device__ float  g_g1[(size_t)MAXN * D1];   // relu(gat1)
__device__ __half g_h2[(size_t)MAXN * D2];   // g1@W2 (fp16)
__device__ float  g_g2[(size_t)MAXN * D2];   // relu(gat2)
__device__ float  g_h3[(size_t)MAXN * 2];
__device__ float  g_as[MAXN];                // alpha_src (accumulated by GEMM epilogue)
__device__ float  g_ad[MAXN];                // alpha_dst
__device__ int    g_counts[MAXN];
__device__ int    g_rowptr[MAXN + 1];
__device__ int    g_colsrc[MAXE];
__device__ float  g_w1t[FIN * D1];           // W1^T [N][K] for n-major smem B
__device__ float  g_w2t[D1 * D2];            // W2^T

__device__ __forceinline__ float leaky(float x) { return x > 0.f ? x : 0.2f * x; }

// ---------------- CSR build (edge_index is INT32) ----------------
__global__ void hist_kernel(const int* __restrict__ ei, int E) {
    int i = blockIdx.x * blockDim.x + threadIdx.x;
    if (i < E) atomicAdd(&g_counts[ei[E + i]], 1);
}

__global__ void scan_kernel(int N) {
    __shared__ int sums[1024];
    int t = threadIdx.x;
    int chunk = (N + 1023) >> 10;
    int beg = t * chunk, end = min(beg + chunk, N);
    int s = 0;
    for (int i = beg; i < end; i++) s += g_counts[i];
    sums[t] = s;
    __syncthreads();
    for (int off = 1; off < 1024; off <<= 1) {
        int v = (t >= off) ? sums[t - off] : 0;
        __syncthreads();
        sums[t] += v;
        __syncthreads();
    }
    int run = (t == 0) ? 0 : sums[t - 1];
    for (int i = beg; i < end; i++) { g_rowptr[i] = run; run += g_counts[i]; }
    if (t == 0) g_rowptr[N] = sums[1023];
}

__global__ void scatter_kernel(const int* __restrict__ ei, int E) {
    int i = blockIdx.x * blockDim.x + threadIdx.x;
    if (i < E) {
        int s = ei[i];
        int d = ei[E + i];
        int pos = g_rowptr[d] + atomicAdd(&g_counts[d], 1);
        g_colsrc[pos] = s;
    }
}

// ---------------- weight transpose: Wt[n][k] = W[k][n] ----------------
__global__ void transpose_kernel(const float* __restrict__ W, float* __restrict__ Wt,
                                 int K, int N) {
    int i = blockIdx.x * blockDim.x + threadIdx.x;
    if (i < K * N) {
        int k = i / N, n = i % N;
        Wt[(size_t)n * K + k] = W[i];
    }
}

// ---------------- TF32 GEMM: ldmatrix fragments, fp16 C, fused alpha ---------
__device__ __forceinline__ void mma_tf32(float* c, const unsigned* a, const unsigned* b) {
    asm volatile(
        "mma.sync.aligned.m16n8k8.row.col.f32.tf32.tf32.f32 "
        "{%0,%1,%2,%3}, {%4,%5,%6,%7}, {%8,%9}, {%0,%1,%2,%3};\n"
        : "+f"(c[0]), "+f"(c[1]), "+f"(c[2]), "+f"(c[3])
        : "r"(a[0]), "r"(a[1]), "r"(a[2]), "r"(a[3]), "r"(b[0]), "r"(b[1]));
}

__device__ __forceinline__ void ldsm_x4(unsigned& r0, unsigned& r1, unsigned& r2,
                                        unsigned& r3, unsigned addr) {
    asm volatile("ldmatrix.sync.aligned.m8n8.x4.shared.b16 {%0,%1,%2,%3}, [%4];\n"
                 : "=r"(r0), "=r"(r1), "=r"(r2), "=r"(r3) : "r"(addr));
}

__device__ __forceinline__ void cp16(unsigned dst, const void* src, bool valid) {
    asm volatile("cp.async.cg.shared.global [%0], [%1], 16, %2;\n"
                 :: "r"(dst), "l"(src), "r"(valid ? 16 : 0));
}

// 128x128 block tile, BK=16, 8 warps (4x2), warp tile 32x64, 4 smem stages.
// A [BM][BK] row-major; B given TRANSPOSED (Bt [N][K]) -> smem Bt [BN][BK].
// Fragments via ldmatrix.x4.b16 (tf32 words as b16 pairs). Numerics identical
// to scalar-LDS TF32 version.
__global__ void __launch_bounds__(256)
gemm_tf32_kernel(const float* __restrict__ A, const float* __restrict__ Bt,
                 __half* __restrict__ C,
                 const float* __restrict__ a_s, const float* __restrict__ a_d,
                 int M, int N, int K) {
    constexpr int BM = 128, BN = 128, BK = 16, S = 4;
    constexpr int ASTR = BK + 4;   // 20 words -> conflict-free LDSM rows
    __shared__ float As[S][BM][ASTR];
    __shared__ float Bs[S][BN][ASTR];

    int tid = threadIdx.x;
    int wid = tid >> 5, lane = tid & 31;
    int g = lane >> 2, tg = lane & 3;
    int warpM = wid & 3, warpN = wid >> 2;
    int m0 = blockIdx.x * BM, n0 = blockIdx.y * BN;
    int wm = warpM * 32, wn = warpN * 64;

    // ldmatrix per-lane address components
    int arow = lane & 15;                 // A: rows r..r+15
    int acol = (lane >> 4) << 2;          // A: col kk or kk+4
    int brow = (lane & 7) + ((lane >> 4) & 1) * 8;   // B: row block
    int bcol = ((lane >> 3) & 1) << 2;               // B: col kk or kk+4

    unsigned asBase = (unsigned)__cvta_generic_to_shared(&As[0][0][0]);
    unsigned bsBase = (unsigned)__cvta_generic_to_shared(&Bs[0][0][0]);
    constexpr unsigned STAGE_A = BM * ASTR * 4;   // bytes per A stage
    constexpr unsigned STAGE_B = BN * ASTR * 4;

    float acc[2][8][4];
#pragma unroll
    for (int mi = 0; mi < 2; mi++)
#pragma unroll
        for (int ni = 0; ni < 8; ni++)
#pragma unroll
            for (int r = 0; r < 4; r++) acc[mi][ni][r] = 0.f;

    int ldr = tid >> 2;            // load row (both tiles: 128 rows, 2 per thread... )
    int ldc = (tid & 3) << 2;      // 4 16B chunks per 64B row

    auto issue = [&](int s, int k0) {
#pragma unroll
        for (int u = 0; u < 2; u++) {
            int row = ldr + u * 64;
            bool v = (m0 + row) < M;
            unsigned d = (unsigned)__cvta_generic_to_shared(&As[s][row][ldc]);
            cp16(d, A + (size_t)(m0 + row) * K + k0 + ldc, v);
        }
#pragma unroll
        for (int u = 0; u < 2; u++) {
            int row = ldr + u * 64;
            unsigned d = (unsigned)__cvta_generic_to_shared(&Bs[s][row][ldc]);
            cp16(d, Bt + (size_t)(n0 + row) * K + k0 + ldc, true);
        }
        asm volatile("cp.async.commit_group;\n");
    };

    int nk = K / BK;
    issue(0, 0);
    if (nk > 1) issue(1, BK); else asm volatile("cp.async.commit_group;\n");
    if (nk > 2) issue(2, 2 * BK); else asm volatile("cp.async.commit_group;\n");

    for (int t = 0; t < nk; t++) {
        int s = t % S;
        asm volatile("cp.async.wait_group 2;\n");
        __syncthreads();
        if (t + 3 < nk) issue((t + 3) % S, (t + 3) * BK);
        else asm volatile("cp.async.commit_group;\n");

        unsigned aStage = asBase + (unsigned)s * STAGE_A;
        unsigned bStage = bsBase + (unsigned)s * STAGE_B;
#pragma unroll
        for (int kk = 0; kk < BK; kk += 8) {
            unsigned a[2][4], b[8][2];
#pragma unroll
            for (int mi = 0; mi < 2; mi++) {
                unsigned addr = aStage +
                    (unsigned)(((wm + mi * 16 + arow) * ASTR + kk + acol) * 4);
                ldsm_x4(a[mi][0], a[mi][1], a[mi][2], a[mi][3], addr);
            }
#pragma unroll
            for (int j = 0; j < 4; j++) {
                unsigned addr = bStage +
                    (unsigned)(((wn + j * 16 + brow) * ASTR + kk + bcol) * 4);
                ldsm_x4(b[2 * j][0], b[2 * j][1], b[2 * j + 1][0], b[2 * j + 1][1], addr);
            }
#pragma unroll
            for (int mi = 0; mi < 2; mi++)
#pragma unroll
                for (int ni = 0; ni < 8; ni++)
                    mma_tf32(acc[mi][ni], a[mi], b[ni]);
        }
    }
    __syncthreads();

    // epilogue: fp16 C + fused alpha partials
#pragma unroll
    for (int mi = 0; mi < 2; mi++) {
        int r0 = m0 + wm + mi * 16 + g;
        int r1 = r0 + 8;
        float ps0 = 0.f, pd0 = 0.f, ps1 = 0.f, pd1 = 0.f;
#pragma unroll
        for (int ni = 0; ni < 8; ni++) {
            int col = n0 + wn + ni * 8 + tg * 2;
            float s0 = a_s[col], s1 = a_s[col + 1];
            float d0 = a_d[col], d1 = a_d[col + 1];
            ps0 += acc[mi][ni][0] * s0 + acc[mi][ni][1] * s1;
            pd0 += acc[mi][ni][0] * d0 + acc[mi][ni][1] * d1;
            ps1 += acc[mi][ni][2] * s0 + acc[mi][ni][3] * s1;
            pd1 += acc[mi][ni][2] * d0 + acc[mi][ni][3] * d1;
            if (r0 < M)
                *(__half2*)(C + (size_t)r0 * N + col) =
                    __floats2half2_rn(acc[mi][ni][0], acc[mi][ni][1]);
            if (r1 < M)
                *(__half2*)(C + (size_t)r1 * N + col) =
                    __floats2half2_rn(acc[mi][ni][2], acc[mi][ni][3]);
        }
        ps0 += __shfl_xor_sync(~0u, ps0, 1); ps0 += __shfl_xor_sync(~0u, ps0, 2);
        pd0 += __shfl_xor_sync(~0u, pd0, 1); pd0 += __shfl_xor_sync(~0u, pd0, 2);
        ps1 += __shfl_xor_sync(~0u, ps1, 1); ps1 += __shfl_xor_sync(~0u, ps1, 2);
        pd1 += __shfl_xor_sync(~0u, pd1, 1); pd1 += __shfl_xor_sync(~0u, pd1, 2);
        if (tg == 0) {
            if (r0 < M) { atomicAdd(&g_as[r0], ps0); atomicAdd(&g_ad[r0], pd0); }
            if (r1 < M) { atomicAdd(&g_as[r1], ps1); atomicAdd(&g_ad[r1], pd1); }
        }
    }
}

// ---------------- fused GAT aggregation (fp16 h gathers, unroll 8) ----------
template <int D, bool RELU>
__global__ void aggregate_kernel(const __half* __restrict__ h,
                                 const float* __restrict__ bias,
                                 float* __restrict__ out, int N) {
    int v = (blockIdx.x * blockDim.x + threadIdx.x) >> 5;
    if (v >= N) return;
    int lane = threadIdx.x & 31;
    float adv = g_ad[v];
    float e_self = leaky(g_as[v] + adv);
    int beg = g_rowptr[v], end = g_rowptr[v + 1];

    // pass 1: max (lanes parallel over edges)
    float m = e_self;
    for (int j = beg + lane; j < end; j += 32)
        m = fmaxf(m, leaky(g_as[g_colsrc[j]] + adv));
    for (int o = 16; o; o >>= 1) m = fmaxf(m, __shfl_xor_sync(~0u, m, o));

    // pass 2: every lane walks all edges; s is lane-redundant
    constexpr int H2 = D / 64;
    float wself = __expf(e_self - m);
    float s = wself;
    float2 acc[H2];
    {
        const __half2* hr = (const __half2*)(h + (size_t)v * D);
#pragma unroll
        for (int i = 0; i < H2; i++) {
            float2 t = __half22float2(hr[lane * H2 + i]);
            acc[i].x = wself * t.x; acc[i].y = wself * t.y;
        }
    }
    int j = beg;
    for (; j + 8 <= end; j += 8) {
        int sid[8];
#pragma unroll
        for (int u = 0; u < 8; u++) sid[u] = g_colsrc[j + u];
        float w[8];
#pragma unroll
        for (int u = 0; u < 8; u++) {
            w[u] = __expf(leaky(g_as[sid[u]] + adv) - m);
            s += w[u];
        }
        __half2 t[8][H2];
#pragma unroll
        for (int u = 0; u < 8; u++) {
            const __half2* p = (const __half2*)(h + (size_t)sid[u] * D);
#pragma unroll
            for (int i = 0; i < H2; i++) t[u][i] = p[lane * H2 + i];
        }
#pragma unroll
        for (int u = 0; u < 8; u++)
#pragma unroll
            for (int i = 0; i < H2; i++) {
                float2 f = __half22float2(t[u][i]);
                acc[i].x = fmaf(w[u], f.x, acc[i].x);
                acc[i].y = fmaf(w[u], f.y, acc[i].y);
            }
    }
    for (; j < end; j++) {
        int srcid = g_colsrc[j];
        float w = __expf(leaky(g_as[srcid] + adv) - m);
        s += w;
        const __half2* hs = (const __half2*)(h + (size_t)srcid * D);
#pragma unroll
        for (int i = 0; i < H2; i++) {
            float2 f = __half22float2(hs[lane * H2 + i]);
            acc[i].x = fmaf(w, f.x, acc[i].x);
            acc[i].y = fmaf(w, f.y, acc[i].y);
        }
    }
    float invs = 1.f / s;
    const float2* b2p = (const float2*)bias;
    float2* o2p = (float2*)(out + (size_t)v * D);
#pragma unroll
    for (int i = 0; i < H2; i++) {
        float2 b = b2p[lane * H2 + i];
        float2 r;
        r.x = acc[i].x * invs + b.x;
        r.y = acc[i].y * invs + b.y;
        if (RELU) { r.x = fmaxf(r.x, 0.f); r.y = fmaxf(r.y, 0.f); }
        o2p[lane * H2 + i] = r;
    }
}

// ---------------- layer 3 projection (256 -> 2) + its alphas ----------------
__global__ void layer3_kernel(const float* __restrict__ g2,
                              const float* __restrict__ W3,
                              const float* __restrict__ a3s,
                              const float* __restrict__ a3d, int N) {
    int v = (blockIdx.x * blockDim.x + threadIdx.x) >> 5;
    if (v >= N) return;
    int lane = threadIdx.x & 31;
    const float* row = g2 + (size_t)v * D2;
    float c0 = 0.f, c1 = 0.f;
#pragma unroll
    for (int i = 0; i < D2 / 32; i++) {
        int k = lane + 32 * i;
        float hv = row[k];
        c0 = fmaf(hv, W3[2 * k], c0);
        c1 = fmaf(hv, W3[2 * k + 1], c1);
    }
    for (int o = 16; o; o >>= 1) {
        c0 += __shfl_xor_sync(~0u, c0, o);
        c1 += __shfl_xor_sync(~0u, c1, o);
    }
    if (lane == 0) {
        g_h3[2 * v] = c0;
        g_h3[2 * v + 1] = c1;
        g_as[v] = c0 * a3s[0] + c1 * a3s[1];
        g_ad[v] = c0 * a3d[0] + c1 * a3d[1];
    }
}

// ---------------- layer 3 aggregation + final class softmax ----------------
__global__ void final_kernel(const float* __restrict__ b3, float* __restrict__ out, int N) {
    int v = (blockIdx.x * blockDim.x + threadIdx.x) >> 5;
    if (v >= N) return;
    int lane = threadIdx.x & 31;
    float adv = g_ad[v];
    float e_self = leaky(g_as[v] + adv);
    int beg = g_rowptr[v], end = g_rowptr[v + 1];

    float m = e_self;
    for (int j = beg + lane; j < end; j += 32)
        m = fmaxf(m, leaky(g_as[g_colsrc[j]] + adv));
    for (int o = 16; o; o >>= 1) m = fmaxf(m, __shfl_xor_sync(~0u, m, o));

    float s = 0.f, a0 = 0.f, a1 = 0.f;
    for (int j = beg + lane; j < end; j += 32) {
        int srcid = g_colsrc[j];
        float w = __expf(leaky(g_as[srcid] + adv) - m);
        s += w;
        a0 = fmaf(w, g_h3[2 * srcid], a0);
        a1 = fmaf(w, g_h3[2 * srcid + 1], a1);
    }
    for (int o = 16; o; o >>= 1) {
        s  += __shfl_xor_sync(~0u, s, o);
        a0 += __shfl_xor_sync(~0u, a0, o);
        a1 += __shfl_xor_sync(~0u, a1, o);
    }
    if (lane == 0) {
        float wself = __expf(e_self - m);
        s += wself;
        a0 += wself * g_h3[2 * v];
        a1 += wself * g_h3[2 * v + 1];
        float invs = 1.f / s;
        float o0 = a0 * invs + b3[0];
        float o1 = a1 * invs + b3[1];
        float mm = fmaxf(o0, o1);
        float z0 = __expf(o0 - mm);
        float z1 = __expf(o1 - mm);
        float zs = z0 + z1;
        out[2 * v]     = z0 / zs;
        out[2 * v + 1] = z1 / zs;
    }
}

// ---------------- launch ----------------
extern "C" void kernel_launch(void* const* d_in, const int* in_sizes, int n_in,
                              void* d_out, int out_size) {
    const float* x   = (const float*)d_in[0];
    const int*   ei  = (const int*)d_in[1];    // int32 (jax x64 disabled)
    const float* W1  = (const float*)d_in[3];
    const float* a1s = (const float*)d_in[4];
    const float* a1d = (const float*)d_in[5];
    const float* b1  = (const float*)d_in[6];
    const float* W2  = (const float*)d_in[7];
    const float* a2s = (const float*)d_in[8];
    const float* a2d = (const float*)d_in[9];
    const float* b2  = (const float*)d_in[10];
    const float* W3  = (const float*)d_in[11];
    const float* a3s = (const float*)d_in[12];
    const float* a3d = (const float*)d_in[13];
    const float* b3  = (const float*)d_in[14];

    int N = in_sizes[2];
    int E = in_sizes[1] / 2;

    __half *h1, *h2;
    float *g1, *g2, *as, *ad, *w1t, *w2t;
    int* counts;
    cudaGetSymbolAddress((void**)&h1, g_h1);
    cudaGetSymbolAddress((void**)&g1, g_g1);
    cudaGetSymbolAddress((void**)&h2, g_h2);
    cudaGetSymbolAddress((void**)&g2, g_g2);
    cudaGetSymbolAddress((void**)&as, g_as);
    cudaGetSymbolAddress((void**)&ad, g_ad);
    cudaGetSymbolAddress((void**)&w1t, g_w1t);
    cudaGetSymbolAddress((void**)&w2t, g_w2t);
    cudaGetSymbolAddress((void**)&counts, g_counts);

    int eb = (E + 255) / 256;
    int nodeWarpBlocks = (N + 7) / 8;
    int gemmRows = (N + 127) / 128;

    // weight transposes (n-major B for ldmatrix)
    transpose_kernel<<<(FIN * D1 + 255) / 256, 256>>>(W1, w1t, FIN, D1);
    transpose_kernel<<<(D1 * D2 + 255) / 256, 256>>>(W2, w2t, D1, D2);

    // CSR build
    cudaMemsetAsync(counts, 0, N * sizeof(int));
    hist_kernel<<<eb, 256>>>(ei, E);
    scan_kernel<<<1, 1024>>>(N);
    cudaMemsetAsync(counts, 0, N * sizeof(int));
    scatter_kernel<<<eb, 256>>>(ei, E);

    // layer 1 (alpha fused into GEMM epilogue; zero accumulators first)
    cudaMemsetAsync(as, 0, N * sizeof(float));
    cudaMemsetAsync(ad, 0, N * sizeof(float));
    gemm_tf32_kernel<<<dim3(gemmRows, 1), 256>>>(x, w1t, h1, a1s, a1d, N, D1, FIN);
    aggregate_kernel<D1, true><<<nodeWarpBlocks, 256>>>(h1, b1, g1, N);

    // layer 2
    cudaMemsetAsync(as, 0, N * sizeof(float));
    cudaMemsetAsync(ad, 0, N * sizeof(float));
    gemm_tf32_kernel<<<dim3(gemmRows, 2), 256>>>(g1, w2t, h2, a2s, a2d, N, D2, D1);
    aggregate_kernel<D2, true><<<nodeWarpBlocks, 256>>>(h2, b2, g2, N);

    // layer 3 + output softmax
    layer3_kernel<<<nodeWarpBlocks, 256>>>(g2, W3, a3s, a3d, N);
    final_kernel<<<nodeWarpBlocks, 256>>>(b3, (float*)d_out, N);
}

// round 16
// speedup vs baseline: 1.2031x; 1.2031x over previous
#include <cuda_runtime.h>
#include <cuda_fp16.h>
#include <cstdint>

// Problem dims (fixed for this dataset)
#define MAXN 100000
#define MAXE 1600000
#define FIN  784
#define D1   128
#define D2   256

// ---------------- scratch (device globals; no allocs allowed) ----------------
__device__ __half g_h1[(size_t)MAXN * D1];   // x@W1 (fp16, gather payload)
__device__ float  g_g1[(size_t)MAXN * D1];   // relu(gat1)
__device__ __half g_h2[(size_t)MAXN * D2];   // g1@W2 (fp16)
__device__ float  g_g2[(size_t)MAXN * D2];   // relu(gat2)
__device__ float  g_h3[(size_t)MAXN * 2];
__device__ float  g_as[MAXN];                // alpha_src (accumulated by GEMM epilogue)
__device__ float  g_ad[MAXN];                // alpha_dst
__device__ int    g_counts[MAXN];
__device__ int    g_rowptr[MAXN + 1];
__device__ int    g_colsrc[MAXE];
__device__ float  g_w1t[FIN * D1];           // W1^T [N][K] for n-major smem B
__device__ float  g_w2t[D1 * D2];            // W2^T
__device__ int    g_blockSum[1024];
__device__ int    g_blockOff[1024];

__device__ __forceinline__ float leaky(float x) { return x > 0.f ? x : 0.2f * x; }

// ---------------- CSR build (edge_index is INT32) ----------------
__global__ void hist_kernel(const int* __restrict__ ei, int E) {
    int i = blockIdx.x * blockDim.x + threadIdx.x;
    if (i < E) atomicAdd(&g_counts[ei[E + i]], 1);
}

// ---- parallel scan over g_counts -> g_rowptr (3 phases, 1024 elems/chunk) ----
__global__ void scanA_kernel(int N) {            // grid = nChunks, block = 256
    int b = blockIdx.x, t = threadIdx.x;
    int base = b * 1024 + t * 4;
    int s = 0;
#pragma unroll
    for (int u = 0; u < 4; u++) {
        int i = base + u;
        if (i < N) s += g_counts[i];
    }
    __shared__ int sh[256];
    sh[t] = s;
    __syncthreads();
    for (int o = 128; o; o >>= 1) {
        if (t < o) sh[t] += sh[t + o];
        __syncthreads();
    }
    if (t == 0) g_blockSum[b] = sh[0];
}

__global__ void scanB_kernel(int nChunks, int N) {   // 1 block, 1024 threads
    __shared__ int sh[1024];
    int t = threadIdx.x;
    sh[t] = (t < nChunks) ? g_blockSum[t] : 0;
    __syncthreads();
    for (int o = 1; o < 1024; o <<= 1) {
        int v = (t >= o) ? sh[t - o] : 0;
        __syncthreads();
        sh[t] += v;
        __syncthreads();
    }
    if (t < nChunks) g_blockOff[t] = (t == 0) ? 0 : sh[t - 1];
    if (t == 0) g_rowptr[N] = sh[1023];
}

__global__ void scanC_kernel(int N) {            // grid = nChunks, block = 256
    int b = blockIdx.x, t = threadIdx.x;
    int base = b * 1024 + t * 4;
    int v[4];
    int s = 0;
#pragma unroll
    for (int u = 0; u < 4; u++) {
        int i = base + u;
        v[u] = (i < N) ? g_counts[i] : 0;
        s += v[u];
    }
    __shared__ int sh[256];
    sh[t] = s;
    __syncthreads();
    for (int o = 1; o < 256; o <<= 1) {
        int x = (t >= o) ? sh[t - o] : 0;
        __syncthreads();
        sh[t] += x;
        __syncthreads();
    }
    int run = g_blockOff[b] + ((t == 0) ? 0 : sh[t - 1]);
#pragma unroll
    for (int u = 0; u < 4; u++) {
        int i = base + u;
        if (i < N) { g_rowptr[i] = run; run += v[u]; }
    }
}

__global__ void scatter_kernel(const int* __restrict__ ei, int E) {
    int i = blockIdx.x * blockDim.x + threadIdx.x;
    if (i < E) {
        int s = ei[i];
        int d = ei[E + i];
        int pos = g_rowptr[d] + atomicAdd(&g_counts[d], 1);
        g_colsrc[pos] = s;
    }
}

// ---------------- weight transpose: Wt[n][k] = W[k][n] ----------------
__global__ void transpose_kernel(const float* __restrict__ W, float* __restrict__ Wt,
                                 int K, int N) {
    int i = blockIdx.x * blockDim.x + threadIdx.x;
    if (i < K * N) {
        int k = i / N, n = i % N;
        Wt[(size_t)n * K + k] = W[i];
    }
}

// ---------------- TF32 GEMM: ldmatrix fragments, fp16 C, fused alpha ---------
__device__ __forceinline__ void mma_tf32(float* c, const unsigned* a, const unsigned* b) {
    asm volatile(
        "mma.sync.aligned.m16n8k8.row.col.f32.tf32.tf32.f32 "
        "{%0,%1,%2,%3}, {%4,%5,%6,%7}, {%8,%9}, {%0,%1,%2,%3};\n"
        : "+f"(c[0]), "+f"(c[1]), "+f"(c[2]), "+f"(c[3])
        : "r"(a[0]), "r"(a[1]), "r"(a[2]), "r"(a[3]), "r"(b[0]), "r"(b[1]));
}

__device__ __forceinline__ void ldsm_x4(unsigned& r0, unsigned& r1, unsigned& r2,
                                        unsigned& r3, unsigned addr) {
    asm volatile("ldmatrix.sync.aligned.m8n8.x4.shared.b16 {%0,%1,%2,%3}, [%4];\n"
                 : "=r"(r0), "=r"(r1), "=r"(r2), "=r"(r3) : "r"(addr));
}

__device__ __forceinline__ void cp16(unsigned dst, const void* src, bool valid) {
    asm volatile("cp.async.cg.shared.global [%0], [%1], 16, %2;\n"
                 :: "r"(dst), "l"(src), "r"(valid ? 16 : 0));
}

// 128x128 block tile, BK=16, 8 warps (4x2), warp tile 32x64, 4 smem stages.
// A [BM][BK] row-major; B given TRANSPOSED (Bt [N][K]) -> smem Bt [BN][BK].
__global__ void __launch_bounds__(256)
gemm_tf32_kernel(const float* __restrict__ A, const float* __restrict__ Bt,
                 __half* __restrict__ C,
                 const float* __restrict__ a_s, const float* __restrict__ a_d,
                 int M, int N, int K) {
    constexpr int BM = 128, BN = 128, BK = 16, S = 4;
    constexpr int ASTR = BK + 4;   // 20 words -> conflict-free LDSM rows
    __shared__ float As[S][BM][ASTR];
    __shared__ float Bs[S][BN][ASTR];

    int tid = threadIdx.x;
    int wid = tid >> 5, lane = tid & 31;
    int g = lane >> 2, tg = lane & 3;
    int warpM = wid & 3, warpN = wid >> 2;
    int m0 = blockIdx.x * BM, n0 = blockIdx.y * BN;
    int wm = warpM * 32, wn = warpN * 64;

    int arow = lane & 15;
    int acol = (lane >> 4) << 2;
    int brow = (lane & 7) + ((lane >> 4) & 1) * 8;
    int bcol = ((lane >> 3) & 1) << 2;

    unsigned asBase = (unsigned)__cvta_generic_to_shared(&As[0][0][0]);
    unsigned bsBase = (unsigned)__cvta_generic_to_shared(&Bs[0][0][0]);
    constexpr unsigned STAGE_A = BM * ASTR * 4;
    constexpr unsigned STAGE_B = BN * ASTR * 4;

    float acc[2][8][4];
#pragma unroll
    for (int mi = 0; mi < 2; mi++)
#pragma unroll
        for (int ni = 0; ni < 8; ni++)
#pragma unroll
            for (int r = 0; r < 4; r++) acc[mi][ni][r] = 0.f;

    int ldr = tid >> 2;
    int ldc = (tid & 3) << 2;

    auto issue = [&](int s, int k0) {
#pragma unroll
        for (int u = 0; u < 2; u++) {
            int row = ldr + u * 64;
            bool v = (m0 + row) < M;
            unsigned d = (unsigned)__cvta_generic_to_shared(&As[s][row][ldc]);
            cp16(d, A + (size_t)(m0 + row) * K + k0 + ldc, v);
        }
#pragma unroll
        for (int u = 0; u < 2; u++) {
            int row = ldr + u * 64;
            unsigned d = (unsigned)__cvta_generic_to_shared(&Bs[s][row][ldc]);
            cp16(d, Bt + (size_t)(n0 + row) * K + k0 + ldc, true);
        }
        asm volatile("cp.async.commit_group;\n");
    };

    int nk = K / BK;
    issue(0, 0);
    if (nk > 1) issue(1, BK); else asm volatile("cp.async.commit_group;\n");
    if (nk > 2) issue(2, 2 * BK); else asm volatile("cp.async.commit_group;\n");

    for (int t = 0; t < nk; t++) {
        int s = t % S;
        asm volatile("cp.async.wait_group 2;\n");
        __syncthreads();
        if (t + 3 < nk) issue((t + 3) % S, (t + 3) * BK);
        else asm volatile("cp.async.commit_group;\n");

        unsigned aStage = asBase + (unsigned)s * STAGE_A;
        unsigned bStage = bsBase + (unsigned)s * STAGE_B;
#pragma unroll
        for (int kk = 0; kk < BK; kk += 8) {
            unsigned a[2][4], b[8][2];
#pragma unroll
            for (int mi = 0; mi < 2; mi++) {
                unsigned addr = aStage +
                    (unsigned)(((wm + mi * 16 + arow) * ASTR + kk + acol) * 4);
                ldsm_x4(a[mi][0], a[mi][1], a[mi][2], a[mi][3], addr);
            }
#pragma unroll
            for (int j = 0; j < 4; j++) {
                unsigned addr = bStage +
                    (unsigned)(((wn + j * 16 + brow) * ASTR + kk + bcol) * 4);
                ldsm_x4(b[2 * j][0], b[2 * j][1], b[2 * j + 1][0], b[2 * j + 1][1], addr);
            }
#pragma unroll
            for (int mi = 0; mi < 2; mi++)
#pragma unroll
                for (int ni = 0; ni < 8; ni++)
                    mma_tf32(acc[mi][ni], a[mi], b[ni]);
        }
    }
    __syncthreads();

    // epilogue: fp16 C + fused alpha partials
#pragma unroll
    for (int mi = 0; mi < 2; mi++) {
        int r0 = m0 + wm + mi * 16 + g;
        int r1 = r0 + 8;
        float ps0 = 0.f, pd0 = 0.f, ps1 = 0.f, pd1 = 0.f;
#pragma unroll
        for (int ni = 0; ni < 8; ni++) {
            int col = n0 + wn + ni * 8 + tg * 2;
            float s0 = a_s[col], s1 = a_s[col + 1];
            float d0 = a_d[col], d1 = a_d[col + 1];
            ps0 += acc[mi][ni][0] * s0 + acc[mi][ni][1] * s1;
            pd0 += acc[mi][ni][0] * d0 + acc[mi][ni][1] * d1;
            ps1 += acc[mi][ni][2] * s0 + acc[mi][ni][3] * s1;
            pd1 += acc[mi][ni][2] * d0 + acc[mi][ni][3] * d1;
            if (r0 < M)
                *(__half2*)(C + (size_t)r0 * N + col) =
                    __floats2half2_rn(acc[mi][ni][0], acc[mi][ni][1]);
            if (r1 < M)
                *(__half2*)(C + (size_t)r1 * N + col) =
                    __floats2half2_rn(acc[mi][ni][2], acc[mi][ni][3]);
        }
        ps0 += __shfl_xor_sync(~0u, ps0, 1); ps0 += __shfl_xor_sync(~0u, ps0, 2);
        pd0 += __shfl_xor_sync(~0u, pd0, 1); pd0 += __shfl_xor_sync(~0u, pd0, 2);
        ps1 += __shfl_xor_sync(~0u, ps1, 1); ps1 += __shfl_xor_sync(~0u, ps1, 2);
        pd1 += __shfl_xor_sync(~0u, pd1, 1); pd1 += __shfl_xor_sync(~0u, pd1, 2);
        if (tg == 0) {
            if (r0 < M) { atomicAdd(&g_as[r0], ps0); atomicAdd(&g_ad[r0], pd0); }
            if (r1 < M) { atomicAdd(&g_as[r1], ps1); atomicAdd(&g_ad[r1], pd1); }
        }
    }
}

// ---------------- fused GAT aggregation (fp16 h gathers, unroll 8) ----------
template <int D, bool RELU>
__global__ void aggregate_kernel(const __half* __restrict__ h,
                                 const float* __restrict__ bias,
                                 float* __restrict__ out, int N) {
    int v = (blockIdx.x * blockDim.x + threadIdx.x) >> 5;
    if (v >= N) return;
    int lane = threadIdx.x & 31;
    float adv = g_ad[v];
    float e_self = leaky(g_as[v] + adv);
    int beg = g_rowptr[v], end = g_rowptr[v + 1];

    // pass 1: max (lanes parallel over edges)
    float m = e_self;
    for (int j = beg + lane; j < end; j += 32)
        m = fmaxf(m, leaky(g_as[g_colsrc[j]] + adv));
    for (int o = 16; o; o >>= 1) m = fmaxf(m, __shfl_xor_sync(~0u, m, o));

    // pass 2: every lane walks all edges; s is lane-redundant
    constexpr int H2 = D / 64;
    float wself = __expf(e_self - m);
    float s = wself;
    float2 acc[H2];
    {
        const __half2* hr = (const __half2*)(h + (size_t)v * D);
#pragma unroll
        for (int i = 0; i < H2; i++) {
            float2 t = __half22float2(hr[lane * H2 + i]);
            acc[i].x = wself * t.x; acc[i].y = wself * t.y;
        }
    }
    int j = beg;
    for (; j + 8 <= end; j += 8) {
        int sid[8];
#pragma unroll
        for (int u = 0; u < 8; u++) sid[u] = g_colsrc[j + u];
        float w[8];
#pragma unroll
        for (int u = 0; u < 8; u++) {
            w[u] = __expf(leaky(g_as[sid[u]] + adv) - m);
            s += w[u];
        }
        __half2 t[8][H2];
#pragma unroll
        for (int u = 0; u < 8; u++) {
            const __half2* p = (const __half2*)(h + (size_t)sid[u] * D);
#pragma unroll
            for (int i = 0; i < H2; i++) t[u][i] = p[lane * H2 + i];
        }
#pragma unroll
        for (int u = 0; u < 8; u++)
#pragma unroll
            for (int i = 0; i < H2; i++) {
                float2 f = __half22float2(t[u][i]);
                acc[i].x = fmaf(w[u], f.x, acc[i].x);
                acc[i].y = fmaf(w[u], f.y, acc[i].y);
            }
    }
    for (; j < end; j++) {
        int srcid = g_colsrc[j];
        float w = __expf(leaky(g_as[srcid] + adv) - m);
        s += w;
        const __half2* hs = (const __half2*)(h + (size_t)srcid * D);
#pragma unroll
        for (int i = 0; i < H2; i++) {
            float2 f = __half22float2(hs[lane * H2 + i]);
            acc[i].x = fmaf(w, f.x, acc[i].x);
            acc[i].y = fmaf(w, f.y, acc[i].y);
        }
    }
    float invs = 1.f / s;
    const float2* b2p = (const float2*)bias;
    float2* o2p = (float2*)(out + (size_t)v * D);
#pragma unroll
    for (int i = 0; i < H2; i++) {
        float2 b = b2p[lane * H2 + i];
        float2 r;
        r.x = acc[i].x * invs + b.x;
        r.y = acc[i].y * invs + b.y;
        if (RELU) { r.x = fmaxf(r.x, 0.f); r.y = fmaxf(r.y, 0.f); }
        o2p[lane * H2 + i] = r;
    }
}

// ---------------- layer 3 projection (256 -> 2) + its alphas ----------------
__global__ void layer3_kernel(const float* __restrict__ g2,
                              const float* __restrict__ W3,
                              const float* __restrict__ a3s,
                              const float* __restrict__ a3d, int N) {
    int v = (blockIdx.x * blockDim.x + threadIdx.x) >> 5;
    if (v >= N) return;
    int lane = threadIdx.x & 31;
    const float* row = g2 + (size_t)v * D2;
    float c0 = 0.f, c1 = 0.f;
#pragma unroll
    for (int i = 0; i < D2 / 32; i++) {
        int k = lane + 32 * i;
        float hv = row[k];
        c0 = fmaf(hv, W3[2 * k], c0);
        c1 = fmaf(hv, W3[2 * k + 1], c1);
    }
    for (int o = 16; o; o >>= 1) {
        c0 += __shfl_xor_sync(~0u, c0, o);
        c1 += __shfl_xor_sync(~0u, c1, o);
    }
    if (lane == 0) {
        g_h3[2 * v] = c0;
        g_h3[2 * v + 1] = c1;
        g_as[v] = c0 * a3s[0] + c1 * a3s[1];
        g_ad[v] = c0 * a3d[0] + c1 * a3d[1];
    }
}

// ---------------- layer 3 aggregation + final class softmax ----------------
__global__ void final_kernel(const float* __restrict__ b3, float* __restrict__ out, int N) {
    int v = (blockIdx.x * blockDim.x + threadIdx.x) >> 5;
    if (v >= N) return;
    int lane = threadIdx.x & 31;
    float adv = g_ad[v];
    float e_self = leaky(g_as[v] + adv);
    int beg = g_rowptr[v], end = g_rowptr[v + 1];

    float m = e_self;
    for (int j = beg + lane; j < end; j += 32)
        m = fmaxf(m, leaky(g_as[g_colsrc[j]] + adv));
    for (int o = 16; o; o >>= 1) m = fmaxf(m, __shfl_xor_sync(~0u, m, o));

    float s = 0.f, a0 = 0.f, a1 = 0.f;
    for (int j = beg + lane; j < end; j += 32) {
        int srcid = g_colsrc[j];
        float w = __expf(leaky(g_as[srcid] + adv) - m);
        s += w;
        a0 = fmaf(w, g_h3[2 * srcid], a0);
        a1 = fmaf(w, g_h3[2 * srcid + 1], a1);
    }
    for (int o = 16; o; o >>= 1) {
        s  += __shfl_xor_sync(~0u, s, o);
        a0 += __shfl_xor_sync(~0u, a0, o);
        a1 += __shfl_xor_sync(~0u, a1, o);
    }
    if (lane == 0) {
        float wself = __expf(e_self - m);
        s += wself;
        a0 += wself * g_h3[2 * v];
        a1 += wself * g_h3[2 * v + 1];
        float invs = 1.f / s;
        float o0 = a0 * invs + b3[0];
        float o1 = a1 * invs + b3[1];
        float mm = fmaxf(o0, o1);
        float z0 = __expf(o0 - mm);
        float z1 = __expf(o1 - mm);
        float zs = z0 + z1;
        out[2 * v]     = z0 / zs;
        out[2 * v + 1] = z1 / zs;
    }
}

// ---------------- launch ----------------
extern "C" void kernel_launch(void* const* d_in, const int* in_sizes, int n_in,
                              void* d_out, int out_size) {
    const float* x   = (const float*)d_in[0];
    const int*   ei  = (const int*)d_in[1];    // int32 (jax x64 disabled)
    const float* W1  = (const float*)d_in[3];
    const float* a1s = (const float*)d_in[4];
    const float* a1d = (const float*)d_in[5];
    const float* b1  = (const float*)d_in[6];
    const float* W2  = (const float*)d_in[7];
    const float* a2s = (const float*)d_in[8];
    const float* a2d = (const float*)d_in[9];
    const float* b2  = (const float*)d_in[10];
    const float* W3  = (const float*)d_in[11];
    const float* a3s = (const float*)d_in[12];
    const float* a3d = (const float*)d_in[13];
    const float* b3  = (const float*)d_in[14];

    int N = in_sizes[2];
    int E = in_sizes[1] / 2;

    __half *h1, *h2;
    float *g1, *g2, *as, *ad, *w1t, *w2t;
    int* counts;
    cudaGetSymbolAddress((void**)&h1, g_h1);
    cudaGetSymbolAddress((void**)&g1, g_g1);
    cudaGetSymbolAddress((void**)&h2, g_h2);
    cudaGetSymbolAddress((void**)&g2, g_g2);
    cudaGetSymbolAddress((void**)&as, g_as);
    cudaGetSymbolAddress((void**)&ad, g_ad);
    cudaGetSymbolAddress((void**)&w1t, g_w1t);
    cudaGetSymbolAddress((void**)&w2t, g_w2t);
    cudaGetSymbolAddress((void**)&counts, g_counts);

    int eb = (E + 255) / 256;
    int nodeWarpBlocks = (N + 7) / 8;
    int gemmRows = (N + 127) / 128;
    int nChunks = (N + 1023) / 1024;

    // weight transposes (n-major B for ldmatrix)
    transpose_kernel<<<(FIN * D1 + 255) / 256, 256>>>(W1, w1t, FIN, D1);
    transpose_kernel<<<(D1 * D2 + 255) / 256, 256>>>(W2, w2t, D1, D2);

    // CSR build (parallel 3-phase scan)
    cudaMemsetAsync(counts, 0, N * sizeof(int));
    hist_kernel<<<eb, 256>>>(ei, E);
    scanA_kernel<<<nChunks, 256>>>(N);
    scanB_kernel<<<1, 1024>>>(nChunks, N);
    scanC_kernel<<<nChunks, 256>>>(N);
    cudaMemsetAsync(counts, 0, N * sizeof(int));
    scatter_kernel<<<eb, 256>>>(ei, E);

    // layer 1 (alpha fused into GEMM epilogue; zero accumulators first)
    cudaMemsetAsync(as, 0, N * sizeof(float));
    cudaMemsetAsync(ad, 0, N * sizeof(float));
    gemm_tf32_kernel<<<dim3(gemmRows, 1), 256>>>(x, w1t, h1, a1s, a1d, N, D1, FIN);
    aggregate_kernel<D1, true><<<nodeWarpBlocks, 256>>>(h1, b1, g1, N);

    // layer 2
    cudaMemsetAsync(as, 0, N * sizeof(float));
    cudaMemsetAsync(ad, 0, N * sizeof(float));
    gemm_tf32_kernel<<<dim3(gemmRows, 2), 256>>>(g1, w2t, h2, a2s, a2d, N, D2, D1);
    aggregate_kernel<D2, true><<<nodeWarpBlocks, 256>>>(h2, b2, g2, N);

    // layer 3 + output softmax
    layer3_kernel<<<nodeWarpBlocks, 256>>>(g2, W3, a3s, a3d, N);
    final_kernel<<<nodeWarpBlocks, 256>>>(b3, (float*)d_out, N);
}

// round 17
// speedup vs baseline: 1.2966x; 1.0777x over previous
#include <cuda_runtime.h>
#include <cuda_fp16.h>
#include <cstdint>

// Problem dims (fixed for this dataset)
#define MAXN 100000
#define MAXE 1600000
#define FIN  784
#define D1   128
#define D2   256

// ---------------- scratch (device globals; no allocs allowed) ----------------
__device__ __half g_h1[(size_t)MAXN * D1];   // x@W1 (fp16, gather payload)
__device__ float  g_g1[(size_t)MAXN * D1];   // relu(gat1)
__device__ __half g_h2[(size_t)MAXN * D2];   // g1@W2 (fp16)
__device__ float  g_g2[(size_t)MAXN * D2];   // relu(gat2)
__device__ float  g_h3[(size_t)MAXN * 2];
__device__ float  g_as[MAXN];                // alpha_src (accumulated by GEMM epilogue)
__device__ float  g_ad[MAXN];                // alpha_dst
__device__ int    g_counts[MAXN];
__device__ int    g_rowptr[MAXN + 1];
__device__ int    g_colsrc[MAXE];
__device__ float  g_w1t[FIN * D1];           // W1^T [N][K] for n-major smem B
__device__ float  g_w2t[D1 * D2];            // W2^T
__device__ int    g_blockSum[1024];
__device__ int    g_blockOff[1024];

__device__ __forceinline__ float leaky(float x) { return x > 0.f ? x : 0.2f * x; }

// ---------------- CSR build (edge_index is INT32) ----------------
__global__ void hist_kernel(const int* __restrict__ ei, int E) {
    int i = blockIdx.x * blockDim.x + threadIdx.x;
    if (i < E) atomicAdd(&g_counts[ei[E + i]], 1);
}

// ---- parallel scan over g_counts -> g_rowptr (3 phases, 1024 elems/chunk) ----
__global__ void scanA_kernel(int N) {            // grid = nChunks, block = 256
    int b = blockIdx.x, t = threadIdx.x;
    int base = b * 1024 + t * 4;
    int s = 0;
#pragma unroll
    for (int u = 0; u < 4; u++) {
        int i = base + u;
        if (i < N) s += g_counts[i];
    }
    __shared__ int sh[256];
    sh[t] = s;
    __syncthreads();
    for (int o = 128; o; o >>= 1) {
        if (t < o) sh[t] += sh[t + o];
        __syncthreads();
    }
    if (t == 0) g_blockSum[b] = sh[0];
}

__global__ void scanB_kernel(int nChunks, int N) {   // 1 block, 1024 threads
    __shared__ int sh[1024];
    int t = threadIdx.x;
    sh[t] = (t < nChunks) ? g_blockSum[t] : 0;
    __syncthreads();
    for (int o = 1; o < 1024; o <<= 1) {
        int v = (t >= o) ? sh[t - o] : 0;
        __syncthreads();
        sh[t] += v;
        __syncthreads();
    }
    if (t < nChunks) g_blockOff[t] = (t == 0) ? 0 : sh[t - 1];
    if (t == 0) g_rowptr[N] = sh[1023];
}

__global__ void scanC_kernel(int N) {            // grid = nChunks, block = 256
    int b = blockIdx.x, t = threadIdx.x;
    int base = b * 1024 + t * 4;
    int v[4];
    int s = 0;
#pragma unroll
    for (int u = 0; u < 4; u++) {
        int i = base + u;
        v[u] = (i < N) ? g_counts[i] : 0;
        s += v[u];
    }
    __shared__ int sh[256];
    sh[t] = s;
    __syncthreads();
    for (int o = 1; o < 256; o <<= 1) {
        int x = (t >= o) ? sh[t - o] : 0;
        __syncthreads();
        sh[t] += x;
        __syncthreads();
    }
    int run = g_blockOff[b] + ((t == 0) ? 0 : sh[t - 1]);
#pragma unroll
    for (int u = 0; u < 4; u++) {
        int i = base + u;
        if (i < N) { g_rowptr[i] = run; run += v[u]; }
    }
}

__global__ void scatter_kernel(const int* __restrict__ ei, int E) {
    int i = blockIdx.x * blockDim.x + threadIdx.x;
    if (i < E) {
        int s = ei[i];
        int d = ei[E + i];
        int pos = g_rowptr[d] + atomicAdd(&g_counts[d], 1);
        g_colsrc[pos] = s;
    }
}

// ---------------- weight transpose: Wt[n][k] = W[k][n] ----------------
__global__ void transpose_kernel(const float* __restrict__ W, float* __restrict__ Wt,
                                 int K, int N) {
    int i = blockIdx.x * blockDim.x + threadIdx.x;
    if (i < K * N) {
        int k = i / N, n = i % N;
        Wt[(size_t)n * K + k] = W[i];
    }
}

// ---------------- TF32 GEMM: ldmatrix fragments, fp16 C, fused alpha ---------
__device__ __forceinline__ void mma_tf32(float* c, const unsigned* a, const unsigned* b) {
    asm volatile(
        "mma.sync.aligned.m16n8k8.row.col.f32.tf32.tf32.f32 "
        "{%0,%1,%2,%3}, {%4,%5,%6,%7}, {%8,%9}, {%0,%1,%2,%3};\n"
        : "+f"(c[0]), "+f"(c[1]), "+f"(c[2]), "+f"(c[3])
        : "r"(a[0]), "r"(a[1]), "r"(a[2]), "r"(a[3]), "r"(b[0]), "r"(b[1]));
}

__device__ __forceinline__ void ldsm_x4(unsigned& r0, unsigned& r1, unsigned& r2,
                                        unsigned& r3, unsigned addr) {
    asm volatile("ldmatrix.sync.aligned.m8n8.x4.shared.b16 {%0,%1,%2,%3}, [%4];\n"
                 : "=r"(r0), "=r"(r1), "=r"(r2), "=r"(r3) : "r"(addr));
}

__device__ __forceinline__ void cp16(unsigned dst, const void* src, bool valid) {
    asm volatile("cp.async.cg.shared.global [%0], [%1], 16, %2;\n"
                 :: "r"(dst), "l"(src), "r"(valid ? 16 : 0));
}

// 128x128 block tile, BK=16, 8 warps (4x2), warp tile 32x64, 4 smem stages.
// A [BM][BK] row-major; B given TRANSPOSED (Bt [N][K]) -> smem Bt [BN][BK].
__global__ void __launch_bounds__(256)
gemm_tf32_kernel(const float* __restrict__ A, const float* __restrict__ Bt,
                 __half* __restrict__ C,
                 const float* __restrict__ a_s, const float* __restrict__ a_d,
                 int M, int N, int K) {
    constexpr int BM = 128, BN = 128, BK = 16, S = 4;
    constexpr int ASTR = BK + 4;   // 20 words -> conflict-free LDSM rows
    __shared__ float As[S][BM][ASTR];
    __shared__ float Bs[S][BN][ASTR];

    int tid = threadIdx.x;
    int wid = tid >> 5, lane = tid & 31;
    int g = lane >> 2, tg = lane & 3;
    int warpM = wid & 3, warpN = wid >> 2;
    int m0 = blockIdx.x * BM, n0 = blockIdx.y * BN;
    int wm = warpM * 32, wn = warpN * 64;

    int arow = lane & 15;
    int acol = (lane >> 4) << 2;
    int brow = (lane & 7) + ((lane >> 4) & 1) * 8;
    int bcol = ((lane >> 3) & 1) << 2;

    unsigned asBase = (unsigned)__cvta_generic_to_shared(&As[0][0][0]);
    unsigned bsBase = (unsigned)__cvta_generic_to_shared(&Bs[0][0][0]);
    constexpr unsigned STAGE_A = BM * ASTR * 4;
    constexpr unsigned STAGE_B = BN * ASTR * 4;

    float acc[2][8][4];
#pragma unroll
    for (int mi = 0; mi < 2; mi++)
#pragma unroll
        for (int ni = 0; ni < 8; ni++)
#pragma unroll
            for (int r = 0; r < 4; r++) acc[mi][ni][r] = 0.f;

    int ldr = tid >> 2;
    int ldc = (tid & 3) << 2;

    auto issue = [&](int s, int k0) {
#pragma unroll
        for (int u = 0; u < 2; u++) {
            int row = ldr + u * 64;
            bool v = (m0 + row) < M;
            unsigned d = (unsigned)__cvta_generic_to_shared(&As[s][row][ldc]);
            cp16(d, A + (size_t)(m0 + row) * K + k0 + ldc, v);
        }
#pragma unroll
        for (int u = 0; u < 2; u++) {
            int row = ldr + u * 64;
            unsigned d = (unsigned)__cvta_generic_to_shared(&Bs[s][row][ldc]);
            cp16(d, Bt + (size_t)(n0 + row) * K + k0 + ldc, true);
        }
        asm volatile("cp.async.commit_group;\n");
    };

    int nk = K / BK;
    issue(0, 0);
    if (nk > 1) issue(1, BK); else asm volatile("cp.async.commit_group;\n");
    if (nk > 2) issue(2, 2 * BK); else asm volatile("cp.async.commit_group;\n");

    for (int t = 0; t < nk; t++) {
        int s = t % S;
        asm volatile("cp.async.wait_group 2;\n");
        __syncthreads();
        if (t + 3 < nk) issue((t + 3) % S, (t + 3) * BK);
        else asm volatile("cp.async.commit_group;\n");

        unsigned aStage = asBase + (unsigned)s * STAGE_A;
        unsigned bStage = bsBase + (unsigned)s * STAGE_B;
#pragma unroll
        for (int kk = 0; kk < BK; kk += 8) {
            unsigned a[2][4], b[8][2];
#pragma unroll
            for (int mi = 0; mi < 2; mi++) {
                unsigned addr = aStage +
                    (unsigned)(((wm + mi * 16 + arow) * ASTR + kk + acol) * 4);
                ldsm_x4(a[mi][0], a[mi][1], a[mi][2], a[mi][3], addr);
            }
#pragma unroll
            for (int j = 0; j < 4; j++) {
                unsigned addr = bStage +
                    (unsigned)(((wn + j * 16 + brow) * ASTR + kk + bcol) * 4);
                ldsm_x4(b[2 * j][0], b[2 * j][1], b[2 * j + 1][0], b[2 * j + 1][1], addr);
            }
#pragma unroll
            for (int mi = 0; mi < 2; mi++)
#pragma unroll
                for (int ni = 0; ni < 8; ni++)
                    mma_tf32(acc[mi][ni], a[mi], b[ni]);
        }
    }
    __syncthreads();

    // epilogue: fp16 C + fused alpha partials
#pragma unroll
    for (int mi = 0; mi < 2; mi++) {
        int r0 = m0 + wm + mi * 16 + g;
        int r1 = r0 + 8;
        float ps0 = 0.f, pd0 = 0.f, ps1 = 0.f, pd1 = 0.f;
#pragma unroll
        for (int ni = 0; ni < 8; ni++) {
            int col = n0 + wn + ni * 8 + tg * 2;
            float s0 = a_s[col], s1 = a_s[col + 1];
            float d0 = a_d[col], d1 = a_d[col + 1];
            ps0 += acc[mi][ni][0] * s0 + acc[mi][ni][1] * s1;
            pd0 += acc[mi][ni][0] * d0 + acc[mi][ni][1] * d1;
            ps1 += acc[mi][ni][2] * s0 + acc[mi][ni][3] * s1;
            pd1 += acc[mi][ni][2] * d0 + acc[mi][ni][3] * d1;
            if (r0 < M)
                *(__half2*)(C + (size_t)r0 * N + col) =
                    __floats2half2_rn(acc[mi][ni][0], acc[mi][ni][1]);
            if (r1 < M)
                *(__half2*)(C + (size_t)r1 * N + col) =
                    __floats2half2_rn(acc[mi][ni][2], acc[mi][ni][3]);
        }
        ps0 += __shfl_xor_sync(~0u, ps0, 1); ps0 += __shfl_xor_sync(~0u, ps0, 2);
        pd0 += __shfl_xor_sync(~0u, pd0, 1); pd0 += __shfl_xor_sync(~0u, pd0, 2);
        ps1 += __shfl_xor_sync(~0u, ps1, 1); ps1 += __shfl_xor_sync(~0u, ps1, 2);
        pd1 += __shfl_xor_sync(~0u, pd1, 1); pd1 += __shfl_xor_sync(~0u, pd1, 2);
        if (tg == 0) {
            if (r0 < M) { atomicAdd(&g_as[r0], ps0); atomicAdd(&g_ad[r0], pd0); }
            if (r1 < M) { atomicAdd(&g_as[r1], ps1); atomicAdd(&g_ad[r1], pd1); }
        }
    }
}

// ---------------- fused GAT aggregation (vectorized fp16 gathers) ------------
// row slice per lane loaded as ONE wide load: uint4 (16B) for D=256, uint2 (8B) for D=128
template <int H2>
__device__ __forceinline__ void ldrow(unsigned* tv, const __half* row, int lane) {
    if (H2 == 4) {
        uint4 q = ((const uint4*)row)[lane];
        tv[0] = q.x; tv[1] = q.y; tv[2] = q.z; tv[3] = q.w;
    } else {
        uint2 q = ((const uint2*)row)[lane];
        tv[0] = q.x; tv[1] = q.y;
    }
}

template <int D, bool RELU>
__global__ void aggregate_kernel(const __half* __restrict__ h,
                                 const float* __restrict__ bias,
                                 float* __restrict__ out, int N) {
    constexpr int H2 = D / 64;
    int v = (blockIdx.x * blockDim.x + threadIdx.x) >> 5;
    if (v >= N) return;
    int lane = threadIdx.x & 31;
    float adv = g_ad[v];
    float e_self = leaky(g_as[v] + adv);
    int beg = g_rowptr[v], end = g_rowptr[v + 1];

    // pass 1: max (lanes parallel over edges)
    float m = e_self;
    for (int j = beg + lane; j < end; j += 32)
        m = fmaxf(m, leaky(g_as[g_colsrc[j]] + adv));
    for (int o = 16; o; o >>= 1) m = fmaxf(m, __shfl_xor_sync(~0u, m, o));

    // pass 2: every lane walks all edges; s is lane-redundant
    float wself = __expf(e_self - m);
    float s = wself;
    float2 acc[H2];
    {
        unsigned tv[4];
        ldrow<H2>(tv, h + (size_t)v * D, lane);
#pragma unroll
        for (int i = 0; i < H2; i++) {
            float2 f = __half22float2(*(__half2*)&tv[i]);
            acc[i].x = wself * f.x; acc[i].y = wself * f.y;
        }
    }
    int j = beg;
    for (; j + 8 <= end; j += 8) {
        int sid[8];
#pragma unroll
        for (int u = 0; u < 8; u++) sid[u] = g_colsrc[j + u];
        float w[8];
#pragma unroll
        for (int u = 0; u < 8; u++) {
            w[u] = __expf(leaky(g_as[sid[u]] + adv) - m);
            s += w[u];
        }
        unsigned t[8][4];
#pragma unroll
        for (int u = 0; u < 8; u++)
            ldrow<H2>(t[u], h + (size_t)sid[u] * D, lane);
#pragma unroll
        for (int u = 0; u < 8; u++)
#pragma unroll
            for (int i = 0; i < H2; i++) {
                float2 f = __half22float2(*(__half2*)&t[u][i]);
                acc[i].x = fmaf(w[u], f.x, acc[i].x);
                acc[i].y = fmaf(w[u], f.y, acc[i].y);
            }
    }
    for (; j < end; j++) {
        int srcid = g_colsrc[j];
        float w = __expf(leaky(g_as[srcid] + adv) - m);
        s += w;
        unsigned tv[4];
        ldrow<H2>(tv, h + (size_t)srcid * D, lane);
#pragma unroll
        for (int i = 0; i < H2; i++) {
            float2 f = __half22float2(*(__half2*)&tv[i]);
            acc[i].x = fmaf(w, f.x, acc[i].x);
            acc[i].y = fmaf(w, f.y, acc[i].y);
        }
    }
    float invs = 1.f / s;
    const float2* b2p = (const float2*)bias;
    float2* o2p = (float2*)(out + (size_t)v * D);
#pragma unroll
    for (int i = 0; i < H2; i++) {
        float2 b = b2p[lane * H2 + i];
        float2 r;
        r.x = acc[i].x * invs + b.x;
        r.y = acc[i].y * invs + b.y;
        if (RELU) { r.x = fmaxf(r.x, 0.f); r.y = fmaxf(r.y, 0.f); }
        o2p[lane * H2 + i] = r;
    }
}

// ---------------- layer 3 projection (256 -> 2) + its alphas ----------------
__global__ void layer3_kernel(const float* __restrict__ g2,
                              const float* __restrict__ W3,
                              const float* __restrict__ a3s,
                              const float* __restrict__ a3d, int N) {
    int v = (blockIdx.x * blockDim.x + threadIdx.x) >> 5;
    if (v >= N) return;
    int lane = threadIdx.x & 31;
    const float* row = g2 + (size_t)v * D2;
    float c0 = 0.f, c1 = 0.f;
#pragma unroll
    for (int i = 0; i < D2 / 32; i++) {
        int k = lane + 32 * i;
        float hv = row[k];
        c0 = fmaf(hv, W3[2 * k], c0);
        c1 = fmaf(hv, W3[2 * k + 1], c1);
    }
    for (int o = 16; o; o >>= 1) {
        c0 += __shfl_xor_sync(~0u, c0, o);
        c1 += __shfl_xor_sync(~0u, c1, o);
    }
    if (lane == 0) {
        g_h3[2 * v] = c0;
        g_h3[2 * v + 1] = c1;
        g_as[v] = c0 * a3s[0] + c1 * a3s[1];
        g_ad[v] = c0 * a3d[0] + c1 * a3d[1];
    }
}

// ---------------- layer 3 aggregation + final class softmax ----------------
__global__ void final_kernel(const float* __restrict__ b3, float* __restrict__ out, int N) {
    int v = (blockIdx.x * blockDim.x + threadIdx.x) >> 5;
    if (v >= N) return;
    int lane = threadIdx.x & 31;
    float adv = g_ad[v];
    float e_self = leaky(g_as[v] + adv);
    int beg = g_rowptr[v], end = g_rowptr[v + 1];

    float m = e_self;
    for (int j = beg + lane; j < end; j += 32)
        m = fmaxf(m, leaky(g_as[g_colsrc[j]] + adv));
    for (int o = 16; o; o >>= 1) m = fmaxf(m, __shfl_xor_sync(~0u, m, o));

    float s = 0.f, a0 = 0.f, a1 = 0.f;
    for (int j = beg + lane; j < end; j += 32) {
        int srcid = g_colsrc[j];
        float w = __expf(leaky(g_as[srcid] + adv) - m);
        s += w;
        a0 = fmaf(w, g_h3[2 * srcid], a0);
        a1 = fmaf(w, g_h3[2 * srcid + 1], a1);
    }
    for (int o = 16; o; o >>= 1) {
        s  += __shfl_xor_sync(~0u, s, o);
        a0 += __shfl_xor_sync(~0u, a0, o);
        a1 += __shfl_xor_sync(~0u, a1, o);
    }
    if (lane == 0) {
        float wself = __expf(e_self - m);
        s += wself;
        a0 += wself * g_h3[2 * v];
        a1 += wself * g_h3[2 * v + 1];
        float invs = 1.f / s;
        float o0 = a0 * invs + b3[0];
        float o1 = a1 * invs + b3[1];
        float mm = fmaxf(o0, o1);
        float z0 = __expf(o0 - mm);
        float z1 = __expf(o1 - mm);
        float zs = z0 + z1;
        out[2 * v]     = z0 / zs;
        out[2 * v + 1] = z1 / zs;
    }
}

// ---------------- launch ----------------
extern "C" void kernel_launch(void* const* d_in, const int* in_sizes, int n_in,
                              void* d_out, int out_size) {
    const float* x   = (const float*)d_in[0];
    const int*   ei  = (const int*)d_in[1];    // int32 (jax x64 disabled)
    const float* W1  = (const float*)d_in[3];
    const float* a1s = (const float*)d_in[4];
    const float* a1d = (const float*)d_in[5];
    const float* b1  = (const float*)d_in[6];
    const float* W2  = (const float*)d_in[7];
    const float* a2s = (const float*)d_in[8];
    const float* a2d = (const float*)d_in[9];
    const float* b2  = (const float*)d_in[10];
    const float* W3  = (const float*)d_in[11];
    const float* a3s = (const float*)d_in[12];
    const float* a3d = (const float*)d_in[13];
    const float* b3  = (const float*)d_in[14];

    int N = in_sizes[2];
    int E = in_sizes[1] / 2;

    __half *h1, *h2;
    float *g1, *g2, *as, *ad, *w1t, *w2t;
    int* counts;
    cudaGetSymbolAddress((void**)&h1, g_h1);
    cudaGetSymbolAddress((void**)&g1, g_g1);
    cudaGetSymbolAddress((void**)&h2, g_h2);
    cudaGetSymbolAddress((void**)&g2, g_g2);
    cudaGetSymbolAddress((void**)&as, g_as);
    cudaGetSymbolAddress((void**)&ad, g_ad);
    cudaGetSymbolAddress((void**)&w1t, g_w1t);
    cudaGetSymbolAddress((void**)&w2t, g_w2t);
    cudaGetSymbolAddress((void**)&counts, g_counts);

    int eb = (E + 255) / 256;
    int nodeWarpBlocks = (N + 7) / 8;
    int gemmRows = (N + 127) / 128;
    int nChunks = (N + 1023) / 1024;

    // weight transposes (n-major B for ldmatrix)
    transpose_kernel<<<(FIN * D1 + 255) / 256, 256>>>(W1, w1t, FIN, D1);
    transpose_kernel<<<(D1 * D2 + 255) / 256, 256>>>(W2, w2t, D1, D2);

    // CSR build (parallel 3-phase scan)
    cudaMemsetAsync(counts, 0, N * sizeof(int));
    hist_kernel<<<eb, 256>>>(ei, E);
    scanA_kernel<<<nChunks, 256>>>(N);
    scanB_kernel<<<1, 1024>>>(nChunks, N);
    scanC_kernel<<<nChunks, 256>>>(N);
    cudaMemsetAsync(counts, 0, N * sizeof(int));
    scatter_kernel<<<eb, 256>>>(ei, E);

    // layer 1 (alpha fused into GEMM epilogue; zero accumulators first)
    cudaMemsetAsync(as, 0, N * sizeof(float));
    cudaMemsetAsync(ad, 0, N * sizeof(float));
    gemm_tf32_kernel<<<dim3(gemmRows, 1), 256>>>(x, w1t, h1, a1s, a1d, N, D1, FIN);
    aggregate_kernel<D1, true><<<nodeWarpBlocks, 256>>>(h1, b1, g1, N);

    // layer 2
    cudaMemsetAsync(as, 0, N * sizeof(float));
    cudaMemsetAsync(ad, 0, N * sizeof(float));
    gemm_tf32_kernel<<<dim3(gemmRows, 2), 256>>>(g1, w2t, h2, a2s, a2d, N, D2, D1);
    aggregate_kernel<D2, true><<<nodeWarpBlocks, 256>>>(h2, b2, g2, N);

    // layer 3 + output softmax
    layer3_kernel<<<nodeWarpBlocks, 256>>>(g2, W3, a3s, a3d, N);
    final_kernel<<<nodeWarpBlocks, 256>>>(b3, (float*)d_out, N);
}